// round 2
// baseline (speedup 1.0000x reference)
#include <cuda_runtime.h>
#include <cuda_bf16.h>
#include <math.h>

#define N_NODES 50000
#define N_EDGES 800000
#define HID 256
#define HEADS 4
#define DH 64
#define NEG 0.2f

#define SCAN_CHUNK 1024
#define NCHUNK ((N_NODES + SCAN_CHUNK - 1) / SCAN_CHUNK)

// ------------------------- device scratch -------------------------
__device__ float g_feat[N_NODES * HID];          // projected features (per layer)
__device__ float g_hA[N_NODES * HID];            // layer-0 output
__device__ float g_hB[N_NODES * HID];            // layer-1 output
__device__ float g_el[N_NODES * HEADS];
__device__ float g_er[N_NODES * HEADS];
__device__ float g_e[(size_t)HEADS * N_EDGES];   // per-head edge scores (CSR slot order)
__device__ int   g_deg[N_NODES];
__device__ int   g_pos[N_NODES];
__device__ int   g_off[N_NODES + 1];
__device__ int   g_srcs[N_EDGES];                // src node per CSR slot
__device__ int   g_chunksum[NCHUNK];
__device__ int   g_chunkoff[NCHUNK];

// ------------------------- CSR build -------------------------
__global__ void zero_kernel() {
    int i = blockIdx.x * blockDim.x + threadIdx.x;
    if (i < N_NODES) { g_deg[i] = 0; g_pos[i] = 0; }
}

__global__ void hist_kernel(const int* __restrict__ dst) {
    int i = blockIdx.x * blockDim.x + threadIdx.x;
    if (i < N_EDGES) atomicAdd(&g_deg[dst[i]], 1);
}

__global__ void scan_chunksum_kernel() {
    __shared__ int sd[256];
    int base = blockIdx.x * SCAN_CHUNK;
    int s = 0;
    for (int i = threadIdx.x; i < SCAN_CHUNK; i += 256) {
        int idx = base + i;
        if (idx < N_NODES) s += g_deg[idx];
    }
    sd[threadIdx.x] = s;
    __syncthreads();
    for (int o = 128; o > 0; o >>= 1) {
        if (threadIdx.x < o) sd[threadIdx.x] += sd[threadIdx.x + o];
        __syncthreads();
    }
    if (threadIdx.x == 0) g_chunksum[blockIdx.x] = sd[0];
}

__global__ void scan_chunkoff_kernel() {
    if (threadIdx.x == 0 && blockIdx.x == 0) {
        int r = 0;
        for (int c = 0; c < NCHUNK; c++) { g_chunkoff[c] = r; r += g_chunksum[c]; }
        g_off[N_NODES] = r;
    }
}

__global__ void scan_final_kernel() {
    __shared__ int sd[SCAN_CHUNK];
    int tid = threadIdx.x;
    int idx = blockIdx.x * SCAN_CHUNK + tid;
    int v = (idx < N_NODES) ? g_deg[idx] : 0;
    sd[tid] = v;
    __syncthreads();
    for (int o = 1; o < SCAN_CHUNK; o <<= 1) {
        int t = (tid >= o) ? sd[tid - o] : 0;
        __syncthreads();
        sd[tid] += t;
        __syncthreads();
    }
    if (idx < N_NODES) g_off[idx] = g_chunkoff[blockIdx.x] + sd[tid] - v;  // exclusive
}

__global__ void scatter_kernel(const int* __restrict__ src, const int* __restrict__ dst) {
    int i = blockIdx.x * blockDim.x + threadIdx.x;
    if (i < N_EDGES) {
        int d = dst[i];
        int p = atomicAdd(&g_pos[d], 1);
        g_srcs[g_off[d] + p] = src[i];
    }
}

// ------------------------- GEMM: C[M,256] = A[M,K] @ B[K,256] -------------------------
// 64x64 tile, BK=16, 256 threads, 4x4 microtile.
#define GBM 64
#define GBN 64
#define GBK 16
__global__ __launch_bounds__(256) void gemm_kernel(
    const float* __restrict__ A, const float* __restrict__ B, float* __restrict__ C,
    int M, int K)
{
    __shared__ float As[GBK][GBM + 1];
    __shared__ float Bs[GBK][GBN];
    const int NN = 256;
    int tid = threadIdx.x;
    int rowBase = blockIdx.y * GBM;
    int colBase = blockIdx.x * GBN;
    int tr = tid >> 4;          // 0..15
    int tc = tid & 15;          // 0..15
    int a_m = tid >> 2;         // 0..63
    int a_k = (tid & 3) * 4;    // 0,4,8,12
    int b_k = tid >> 4;         // 0..15
    int b_c = (tid & 15) * 4;   // 0..60

    float acc[4][4];
#pragma unroll
    for (int i = 0; i < 4; i++)
#pragma unroll
        for (int j = 0; j < 4; j++) acc[i][j] = 0.f;

    for (int k0 = 0; k0 < K; k0 += GBK) {
        float4 av = make_float4(0.f, 0.f, 0.f, 0.f);
        int grow = rowBase + a_m;
        if (grow < M) av = *(const float4*)(A + (size_t)grow * K + k0 + a_k);
        As[a_k + 0][a_m] = av.x;
        As[a_k + 1][a_m] = av.y;
        As[a_k + 2][a_m] = av.z;
        As[a_k + 3][a_m] = av.w;
        float4 bv = *(const float4*)(B + (size_t)(k0 + b_k) * NN + colBase + b_c);
        *(float4*)&Bs[b_k][b_c] = bv;
        __syncthreads();
#pragma unroll
        for (int kk = 0; kk < GBK; kk++) {
            float ar[4], br[4];
#pragma unroll
            for (int i = 0; i < 4; i++) ar[i] = As[kk][tr * 4 + i];
            float4 b4 = *(const float4*)&Bs[kk][tc * 4];
            br[0] = b4.x; br[1] = b4.y; br[2] = b4.z; br[3] = b4.w;
#pragma unroll
            for (int i = 0; i < 4; i++)
#pragma unroll
                for (int j = 0; j < 4; j++) acc[i][j] = fmaf(ar[i], br[j], acc[i][j]);
        }
        __syncthreads();
    }
#pragma unroll
    for (int i = 0; i < 4; i++) {
        int row = rowBase + tr * 4 + i;
        if (row < M) {
#pragma unroll
            for (int j = 0; j < 4; j++)
                C[(size_t)row * NN + colBase + tc * 4 + j] = acc[i][j];
        }
    }
}

// ------------------------- el/er projections -------------------------
// layers 0/1: warp per (node, head), D=64
__global__ __launch_bounds__(256) void elr4_kernel(
    const float* __restrict__ al, const float* __restrict__ ar)
{
    int w = blockIdx.x * 8 + (threadIdx.x >> 5);
    if (w >= N_NODES * HEADS) return;
    int lane = threadIdx.x & 31;
    int n = w >> 2, h = w & 3;
    const float* f = g_feat + (size_t)n * HID + h * DH;
    float f0 = f[lane], f1 = f[lane + 32];
    float a0 = al[h * DH + lane], a1 = al[h * DH + lane + 32];
    float r0 = ar[h * DH + lane], r1 = ar[h * DH + lane + 32];
    float pe = f0 * a0 + f1 * a1;
    float pr = f0 * r0 + f1 * r1;
#pragma unroll
    for (int o = 16; o; o >>= 1) {
        pe += __shfl_xor_sync(0xffffffffu, pe, o);
        pr += __shfl_xor_sync(0xffffffffu, pr, o);
    }
    if (lane == 0) { g_el[w] = pe; g_er[w] = pr; }
}

// layer 2: warp per node, D=256, single head
__global__ __launch_bounds__(256) void elr1_kernel(
    const float* __restrict__ al, const float* __restrict__ ar)
{
    int n = blockIdx.x * 8 + (threadIdx.x >> 5);
    if (n >= N_NODES) return;
    int lane = threadIdx.x & 31;
    const float* f = g_feat + (size_t)n * HID;
    float pe = 0.f, pr = 0.f;
#pragma unroll
    for (int j = 0; j < 8; j++) {
        float fv = f[lane + 32 * j];
        pe += fv * al[lane + 32 * j];
        pr += fv * ar[lane + 32 * j];
    }
#pragma unroll
    for (int o = 16; o; o >>= 1) {
        pe += __shfl_xor_sync(0xffffffffu, pe, o);
        pr += __shfl_xor_sync(0xffffffffu, pr, o);
    }
    if (lane == 0) { g_el[n] = pe; g_er[n] = pr; }
}

// ------------------------- aggregation -------------------------
// layers 0/1: warp per (node, head); edge softmax + gather; relu(msg + b)
__global__ __launch_bounds__(256) void agg4_kernel(
    const float* __restrict__ bvec, float* __restrict__ out)
{
    int w = blockIdx.x * 8 + (threadIdx.x >> 5);
    if (w >= N_NODES * HEADS) return;
    int lane = threadIdx.x & 31;
    int n = w >> 2, h = w & 3;
    int beg = g_off[n], end = g_off[n + 1];
    float ern = g_er[w];
    float* eplane = g_e + (size_t)h * N_EDGES;

    float mx = -3.4e38f;
    for (int i = beg + lane; i < end; i += 32) {
        float ev = g_el[g_srcs[i] * HEADS + h] + ern;
        ev = (ev > 0.f) ? ev : ev * NEG;
        eplane[i] = ev;
        mx = fmaxf(mx, ev);
    }
#pragma unroll
    for (int o = 16; o; o >>= 1) mx = fmaxf(mx, __shfl_xor_sync(0xffffffffu, mx, o));

    float se = 0.f;
    for (int i = beg + lane; i < end; i += 32) {
        float ex = __expf(eplane[i] - mx);
        eplane[i] = ex;
        se += ex;
    }
#pragma unroll
    for (int o = 16; o; o >>= 1) se += __shfl_xor_sync(0xffffffffu, se, o);
    float inv = 1.f / se;
    __syncwarp();   // make eplane writes from all lanes visible

    float acc0 = 0.f, acc1 = 0.f;
    for (int i = beg; i < end; i++) {
        float a = eplane[i] * inv;
        int s = g_srcs[i];
        const float* fr = g_feat + (size_t)s * HID + h * DH;
        acc0 = fmaf(a, fr[lane], acc0);
        acc1 = fmaf(a, fr[lane + 32], acc1);
    }
    float o0 = acc0 + bvec[h * DH + lane];
    float o1 = acc1 + bvec[h * DH + lane + 32];
    out[(size_t)n * HID + h * DH + lane]      = fmaxf(o0, 0.f);
    out[(size_t)n * HID + h * DH + lane + 32] = fmaxf(o1, 0.f);
}

// layer 2: warp per node, single head D=256, no activation (mean over 1 head = identity)
__global__ __launch_bounds__(256) void agg1_kernel(
    const float* __restrict__ bvec, float* __restrict__ out)
{
    int n = blockIdx.x * 8 + (threadIdx.x >> 5);
    if (n >= N_NODES) return;
    int lane = threadIdx.x & 31;
    int beg = g_off[n], end = g_off[n + 1];
    float ern = g_er[n];

    float mx = -3.4e38f;
    for (int i = beg + lane; i < end; i += 32) {
        float ev = g_el[g_srcs[i]] + ern;
        ev = (ev > 0.f) ? ev : ev * NEG;
        g_e[i] = ev;
        mx = fmaxf(mx, ev);
    }
#pragma unroll
    for (int o = 16; o; o >>= 1) mx = fmaxf(mx, __shfl_xor_sync(0xffffffffu, mx, o));

    float se = 0.f;
    for (int i = beg + lane; i < end; i += 32) {
        float ex = __expf(g_e[i] - mx);
        g_e[i] = ex;
        se += ex;
    }
#pragma unroll
    for (int o = 16; o; o >>= 1) se += __shfl_xor_sync(0xffffffffu, se, o);
    float inv = 1.f / se;
    __syncwarp();

    float acc[8];
#pragma unroll
    for (int j = 0; j < 8; j++) acc[j] = 0.f;
    for (int i = beg; i < end; i++) {
        float a = g_e[i] * inv;
        int s = g_srcs[i];
        const float* fr = g_feat + (size_t)s * HID;
#pragma unroll
        for (int j = 0; j < 8; j++) acc[j] = fmaf(a, fr[lane + 32 * j], acc[j]);
    }
#pragma unroll
    for (int j = 0; j < 8; j++)
        out[(size_t)n * HID + lane + 32 * j] = acc[j] + bvec[lane + 32 * j];
}

// ------------------------- host launch -------------------------
extern "C" void kernel_launch(void* const* d_in, const int* in_sizes, int n_in,
                              void* d_out, int out_size)
{
    const float* feats = (const float*)d_in[0];
    const int*   src   = (const int*)d_in[1];
    const int*   dst   = (const int*)d_in[2];
    const float* W0  = (const float*)d_in[3];
    const float* al0 = (const float*)d_in[4];
    const float* ar0 = (const float*)d_in[5];
    const float* b0  = (const float*)d_in[6];
    const float* W1  = (const float*)d_in[7];
    const float* al1 = (const float*)d_in[8];
    const float* ar1 = (const float*)d_in[9];
    const float* b1  = (const float*)d_in[10];
    const float* W2  = (const float*)d_in[11];
    const float* al2 = (const float*)d_in[12];
    const float* ar2 = (const float*)d_in[13];
    const float* b2  = (const float*)d_in[14];
    float* out = (float*)d_out;

    float *p_feat, *p_hA, *p_hB;
    cudaGetSymbolAddress((void**)&p_feat, g_feat);
    cudaGetSymbolAddress((void**)&p_hA, g_hA);
    cudaGetSymbolAddress((void**)&p_hB, g_hB);

    // CSR build
    zero_kernel<<<(N_NODES + 255) / 256, 256>>>();
    hist_kernel<<<(N_EDGES + 255) / 256, 256>>>(dst);
    scan_chunksum_kernel<<<NCHUNK, 256>>>();
    scan_chunkoff_kernel<<<1, 32>>>();
    scan_final_kernel<<<NCHUNK, SCAN_CHUNK>>>();
    scatter_kernel<<<(N_EDGES + 255) / 256, 256>>>(src, dst);

    dim3 ggrid(256 / GBN, (N_NODES + GBM - 1) / GBM);
    int nw4 = (N_NODES * HEADS + 7) / 8;   // blocks for warp-per-(n,h) kernels
    int nw1 = (N_NODES + 7) / 8;

    // layer 0: 512 -> 4x64, relu
    gemm_kernel<<<ggrid, 256>>>(feats, W0, p_feat, N_NODES, 512);
    elr4_kernel<<<nw4, 256>>>(al0, ar0);
    agg4_kernel<<<nw4, 256>>>(b0, p_hA);

    // layer 1: 256 -> 4x64, relu
    gemm_kernel<<<ggrid, 256>>>(p_hA, W1, p_feat, N_NODES, 256);
    elr4_kernel<<<nw4, 256>>>(al1, ar1);
    agg4_kernel<<<nw4, 256>>>(b1, p_hB);

    // layer 2: 256 -> 1x256, no activation
    gemm_kernel<<<ggrid, 256>>>(p_hB, W2, p_feat, N_NODES, 256);
    elr1_kernel<<<nw1, 256>>>(al2, ar2);
    agg1_kernel<<<nw1, 256>>>(b2, out);
}

// round 3
// speedup vs baseline: 1.7736x; 1.7736x over previous
#include <cuda_runtime.h>
#include <cuda_bf16.h>
#include <math.h>

#define N_NODES 50000
#define N_EDGES 800000
#define HID 256
#define HEADS 4
#define DH 64
#define NEG 0.2f

#define SCAN_CHUNK 1024
#define NCHUNK ((N_NODES + SCAN_CHUNK - 1) / SCAN_CHUNK)

// ------------------------- device scratch -------------------------
__device__ float g_feat[N_NODES * HID];          // projected features (per layer)
__device__ float g_hA[N_NODES * HID];            // layer-0 output
__device__ float g_hB[N_NODES * HID];            // layer-1 output
__device__ float g_el[N_NODES * HEADS];
__device__ float g_er[N_NODES * HEADS];
__device__ float g_e[(size_t)HEADS * N_EDGES];   // per-head edge scores (CSR slot order)
__device__ int   g_deg[N_NODES];
__device__ int   g_pos[N_NODES];
__device__ int   g_off[N_NODES + 1];
__device__ int   g_srcs[N_EDGES];                // src node per CSR slot
__device__ int   g_chunksum[NCHUNK];
__device__ int   g_chunkoff[NCHUNK];

// ------------------------- CSR build -------------------------
__global__ void zero_kernel() {
    int i = blockIdx.x * blockDim.x + threadIdx.x;
    if (i < N_NODES) { g_deg[i] = 0; g_pos[i] = 0; }
}

__global__ void hist_kernel(const int* __restrict__ dst) {
    int i = blockIdx.x * blockDim.x + threadIdx.x;
    if (i < N_EDGES) atomicAdd(&g_deg[dst[i]], 1);
}

__global__ void scan_chunksum_kernel() {
    __shared__ int sd[256];
    int base = blockIdx.x * SCAN_CHUNK;
    int s = 0;
    for (int i = threadIdx.x; i < SCAN_CHUNK; i += 256) {
        int idx = base + i;
        if (idx < N_NODES) s += g_deg[idx];
    }
    sd[threadIdx.x] = s;
    __syncthreads();
    for (int o = 128; o > 0; o >>= 1) {
        if (threadIdx.x < o) sd[threadIdx.x] += sd[threadIdx.x + o];
        __syncthreads();
    }
    if (threadIdx.x == 0) g_chunksum[blockIdx.x] = sd[0];
}

// parallel exclusive scan over NCHUNK (<=64) chunk sums
__global__ void scan_chunkoff_kernel() {
    __shared__ int s[64];
    int t = threadIdx.x;
    int v = (t < NCHUNK) ? g_chunksum[t] : 0;
    s[t] = v;
    __syncthreads();
    for (int o = 1; o < 64; o <<= 1) {
        int x = (t >= o) ? s[t - o] : 0;
        __syncthreads();
        s[t] += x;
        __syncthreads();
    }
    if (t < NCHUNK) g_chunkoff[t] = s[t] - v;   // exclusive
    if (t == 63) g_off[N_NODES] = s[63];
}

__global__ void scan_final_kernel() {
    __shared__ int sd[SCAN_CHUNK];
    int tid = threadIdx.x;
    int idx = blockIdx.x * SCAN_CHUNK + tid;
    int v = (idx < N_NODES) ? g_deg[idx] : 0;
    sd[tid] = v;
    __syncthreads();
    for (int o = 1; o < SCAN_CHUNK; o <<= 1) {
        int t = (tid >= o) ? sd[tid - o] : 0;
        __syncthreads();
        sd[tid] += t;
        __syncthreads();
    }
    if (idx < N_NODES) g_off[idx] = g_chunkoff[blockIdx.x] + sd[tid] - v;  // exclusive
}

__global__ void scatter_kernel(const int* __restrict__ src, const int* __restrict__ dst) {
    int i = blockIdx.x * blockDim.x + threadIdx.x;
    if (i < N_EDGES) {
        int d = dst[i];
        int p = atomicAdd(&g_pos[d], 1);
        g_srcs[g_off[d] + p] = src[i];
    }
}

// ------------------------- TF32 tensor-core GEMM -------------------------
// C[M,256] = A[M,K] @ B[K,256].  Block tile 128x64, BK=32, 8 warps (4x2),
// warp tile 32x32 = 2x4 tiles of m16n8k8. XOR-swizzled smem, ping-pong bufs.
#define BM 128
#define BN 64
#define BK 32

__device__ __forceinline__ unsigned f2tf32(float f) {
    unsigned u;
    asm("cvt.rna.tf32.f32 %0, %1;" : "=r"(u) : "f"(f));
    return u;
}

__device__ __forceinline__ void mma_tf32(float* c, const unsigned* a, const unsigned* b) {
    asm volatile(
        "mma.sync.aligned.m16n8k8.row.col.f32.tf32.tf32.f32 "
        "{%0,%1,%2,%3}, {%4,%5,%6,%7}, {%8,%9}, {%0,%1,%2,%3};\n"
        : "+f"(c[0]), "+f"(c[1]), "+f"(c[2]), "+f"(c[3])
        : "r"(a[0]), "r"(a[1]), "r"(a[2]), "r"(a[3]), "r"(b[0]), "r"(b[1]));
}

__global__ __launch_bounds__(256) void gemm_tc_kernel(
    const float* __restrict__ A, const float* __restrict__ B, float* __restrict__ C,
    int M, int K)
{
    __shared__ unsigned As[2][BM * BK];   // swizzled tf32 bits
    __shared__ unsigned Bs[2][BK * BN];

    int tid = threadIdx.x;
    int lane = tid & 31;
    int w = tid >> 5;
    int wm = w >> 1;          // 0..3
    int wn = w & 1;           // 0..1
    int rowBase = blockIdx.y * BM;
    int colBase = blockIdx.x * BN;

    float c[2][4][4];
#pragma unroll
    for (int t = 0; t < 2; t++)
#pragma unroll
        for (int u = 0; u < 4; u++)
#pragma unroll
            for (int j = 0; j < 4; j++) c[t][u][j] = 0.f;

    // gmem load mapping
    int am_ld = tid >> 3;            // 0..31 row within 32-row pass
    int ak_ld = (tid & 7) << 2;      // k4: 0..28
    int bk_ld = tid >> 4;            // 0..15
    int bn_ld = (tid & 15) << 2;     // 0..60

    float4 ra[4];
    float4 rb[2];

#define LOAD_TILE(k0)                                                          \
    {                                                                          \
        _Pragma("unroll")                                                      \
        for (int p = 0; p < 4; p++) {                                          \
            int row = rowBase + p * 32 + am_ld;                                \
            ra[p] = (row < M)                                                  \
                ? *(const float4*)(A + (size_t)row * K + (k0) + ak_ld)         \
                : make_float4(0.f, 0.f, 0.f, 0.f);                             \
        }                                                                      \
        _Pragma("unroll")                                                      \
        for (int p = 0; p < 2; p++) {                                          \
            int kk = (k0) + p * 16 + bk_ld;                                    \
            rb[p] = *(const float4*)(B + (size_t)kk * 256 + colBase + bn_ld);  \
        }                                                                      \
    }

#define STORE_TILE(buf)                                                        \
    {                                                                          \
        _Pragma("unroll")                                                      \
        for (int p = 0; p < 4; p++) {                                          \
            int m = p * 32 + am_ld;                                            \
            int idx = m * BK + (ak_ld ^ ((m & 7) << 2));                       \
            uint4 v;                                                           \
            v.x = f2tf32(ra[p].x); v.y = f2tf32(ra[p].y);                      \
            v.z = f2tf32(ra[p].z); v.w = f2tf32(ra[p].w);                      \
            *(uint4*)&As[buf][idx] = v;                                        \
        }                                                                      \
        _Pragma("unroll")                                                      \
        for (int p = 0; p < 2; p++) {                                          \
            int k = p * 16 + bk_ld;                                            \
            int idx = k * BN + (bn_ld ^ ((k & 3) << 3));                       \
            uint4 v;                                                           \
            v.x = f2tf32(rb[p].x); v.y = f2tf32(rb[p].y);                      \
            v.z = f2tf32(rb[p].z); v.w = f2tf32(rb[p].w);                      \
            *(uint4*)&Bs[buf][idx] = v;                                        \
        }                                                                      \
    }

    int KS = K / BK;
    LOAD_TILE(0);
    STORE_TILE(0);
    __syncthreads();

    for (int it = 0; it < KS; ++it) {
        int cur = it & 1;
        if (it + 1 < KS) LOAD_TILE((it + 1) * BK);

#pragma unroll
        for (int kk = 0; kk < 4; kk++) {
            int kb = kk * 8;
            unsigned af[2][4], bf[4][2];
#pragma unroll
            for (int t = 0; t < 2; t++) {
                int r  = wm * 32 + t * 16 + (lane >> 2);
                int r8 = r + 8;
                int c0 = kb + (lane & 3);
                int sw  = (r  & 7) << 2;
                int sw8 = (r8 & 7) << 2;
                af[t][0] = As[cur][r  * BK + ( c0      ^ sw )];
                af[t][1] = As[cur][r8 * BK + ( c0      ^ sw8)];
                af[t][2] = As[cur][r  * BK + ((c0 + 4) ^ sw )];
                af[t][3] = As[cur][r8 * BK + ((c0 + 4) ^ sw8)];
            }
#pragma unroll
            for (int u = 0; u < 4; u++) {
                int n  = wn * 32 + u * 8 + (lane >> 2);
                int k0 = kb + (lane & 3);
                int k1 = k0 + 4;
                bf[u][0] = Bs[cur][k0 * BN + (n ^ ((k0 & 3) << 3))];
                bf[u][1] = Bs[cur][k1 * BN + (n ^ ((k1 & 3) << 3))];
            }
#pragma unroll
            for (int t = 0; t < 2; t++)
#pragma unroll
                for (int u = 0; u < 4; u++)
                    mma_tf32(c[t][u], af[t], bf[u]);
        }

        if (it + 1 < KS) STORE_TILE((it + 1) & 1);
        __syncthreads();
    }

    // epilogue
#pragma unroll
    for (int t = 0; t < 2; t++) {
        int r  = rowBase + wm * 32 + t * 16 + (lane >> 2);
        int r8 = r + 8;
#pragma unroll
        for (int u = 0; u < 4; u++) {
            int col = colBase + wn * 32 + u * 8 + ((lane & 3) << 1);
            if (r  < M) *(float2*)(C + (size_t)r  * 256 + col) = make_float2(c[t][u][0], c[t][u][1]);
            if (r8 < M) *(float2*)(C + (size_t)r8 * 256 + col) = make_float2(c[t][u][2], c[t][u][3]);
        }
    }
#undef LOAD_TILE
#undef STORE_TILE
}

// ------------------------- el/er projections -------------------------
__global__ __launch_bounds__(256) void elr4_kernel(
    const float* __restrict__ al, const float* __restrict__ ar)
{
    int w = blockIdx.x * 8 + (threadIdx.x >> 5);
    if (w >= N_NODES * HEADS) return;
    int lane = threadIdx.x & 31;
    int n = w >> 2, h = w & 3;
    const float* f = g_feat + (size_t)n * HID + h * DH;
    float f0 = f[lane], f1 = f[lane + 32];
    float a0 = al[h * DH + lane], a1 = al[h * DH + lane + 32];
    float r0 = ar[h * DH + lane], r1 = ar[h * DH + lane + 32];
    float pe = f0 * a0 + f1 * a1;
    float pr = f0 * r0 + f1 * r1;
#pragma unroll
    for (int o = 16; o; o >>= 1) {
        pe += __shfl_xor_sync(0xffffffffu, pe, o);
        pr += __shfl_xor_sync(0xffffffffu, pr, o);
    }
    if (lane == 0) { g_el[w] = pe; g_er[w] = pr; }
}

__global__ __launch_bounds__(256) void elr1_kernel(
    const float* __restrict__ al, const float* __restrict__ ar)
{
    int n = blockIdx.x * 8 + (threadIdx.x >> 5);
    if (n >= N_NODES) return;
    int lane = threadIdx.x & 31;
    const float* f = g_feat + (size_t)n * HID;
    float pe = 0.f, pr = 0.f;
#pragma unroll
    for (int j = 0; j < 8; j++) {
        float fv = f[lane + 32 * j];
        pe += fv * al[lane + 32 * j];
        pr += fv * ar[lane + 32 * j];
    }
#pragma unroll
    for (int o = 16; o; o >>= 1) {
        pe += __shfl_xor_sync(0xffffffffu, pe, o);
        pr += __shfl_xor_sync(0xffffffffu, pr, o);
    }
    if (lane == 0) { g_el[n] = pe; g_er[n] = pr; }
}

// ------------------------- aggregation -------------------------
__global__ __launch_bounds__(256) void agg4_kernel(
    const float* __restrict__ bvec, float* __restrict__ out)
{
    int w = blockIdx.x * 8 + (threadIdx.x >> 5);
    if (w >= N_NODES * HEADS) return;
    int lane = threadIdx.x & 31;
    int n = w >> 2, h = w & 3;
    int beg = g_off[n], end = g_off[n + 1];
    float ern = g_er[w];
    float* eplane = g_e + (size_t)h * N_EDGES;

    float mx = -3.4e38f;
    for (int i = beg + lane; i < end; i += 32) {
        float ev = g_el[g_srcs[i] * HEADS + h] + ern;
        ev = (ev > 0.f) ? ev : ev * NEG;
        eplane[i] = ev;
        mx = fmaxf(mx, ev);
    }
#pragma unroll
    for (int o = 16; o; o >>= 1) mx = fmaxf(mx, __shfl_xor_sync(0xffffffffu, mx, o));

    float se = 0.f;
    for (int i = beg + lane; i < end; i += 32) {
        float ex = __expf(eplane[i] - mx);
        eplane[i] = ex;
        se += ex;
    }
#pragma unroll
    for (int o = 16; o; o >>= 1) se += __shfl_xor_sync(0xffffffffu, se, o);
    float inv = 1.f / se;
    __syncwarp();

    float acc0 = 0.f, acc1 = 0.f;
    for (int i = beg; i < end; i++) {
        float a = eplane[i] * inv;
        int s = g_srcs[i];
        const float* fr = g_feat + (size_t)s * HID + h * DH;
        acc0 = fmaf(a, fr[lane], acc0);
        acc1 = fmaf(a, fr[lane + 32], acc1);
    }
    float o0 = acc0 + bvec[h * DH + lane];
    float o1 = acc1 + bvec[h * DH + lane + 32];
    out[(size_t)n * HID + h * DH + lane]      = fmaxf(o0, 0.f);
    out[(size_t)n * HID + h * DH + lane + 32] = fmaxf(o1, 0.f);
}

__global__ __launch_bounds__(256) void agg1_kernel(
    const float* __restrict__ bvec, float* __restrict__ out)
{
    int n = blockIdx.x * 8 + (threadIdx.x >> 5);
    if (n >= N_NODES) return;
    int lane = threadIdx.x & 31;
    int beg = g_off[n], end = g_off[n + 1];
    float ern = g_er[n];

    float mx = -3.4e38f;
    for (int i = beg + lane; i < end; i += 32) {
        float ev = g_el[g_srcs[i]] + ern;
        ev = (ev > 0.f) ? ev : ev * NEG;
        g_e[i] = ev;
        mx = fmaxf(mx, ev);
    }
#pragma unroll
    for (int o = 16; o; o >>= 1) mx = fmaxf(mx, __shfl_xor_sync(0xffffffffu, mx, o));

    float se = 0.f;
    for (int i = beg + lane; i < end; i += 32) {
        float ex = __expf(g_e[i] - mx);
        g_e[i] = ex;
        se += ex;
    }
#pragma unroll
    for (int o = 16; o; o >>= 1) se += __shfl_xor_sync(0xffffffffu, se, o);
    float inv = 1.f / se;
    __syncwarp();

    float acc[8];
#pragma unroll
    for (int j = 0; j < 8; j++) acc[j] = 0.f;
    for (int i = beg; i < end; i++) {
        float a = g_e[i] * inv;
        int s = g_srcs[i];
        const float* fr = g_feat + (size_t)s * HID;
#pragma unroll
        for (int j = 0; j < 8; j++) acc[j] = fmaf(a, fr[lane + 32 * j], acc[j]);
    }
#pragma unroll
    for (int j = 0; j < 8; j++)
        out[(size_t)n * HID + lane + 32 * j] = acc[j] + bvec[lane + 32 * j];
}

// ------------------------- host launch -------------------------
extern "C" void kernel_launch(void* const* d_in, const int* in_sizes, int n_in,
                              void* d_out, int out_size)
{
    const float* feats = (const float*)d_in[0];
    const int*   src   = (const int*)d_in[1];
    const int*   dst   = (const int*)d_in[2];
    const float* W0  = (const float*)d_in[3];
    const float* al0 = (const float*)d_in[4];
    const float* ar0 = (const float*)d_in[5];
    const float* b0  = (const float*)d_in[6];
    const float* W1  = (const float*)d_in[7];
    const float* al1 = (const float*)d_in[8];
    const float* ar1 = (const float*)d_in[9];
    const float* b1  = (const float*)d_in[10];
    const float* W2  = (const float*)d_in[11];
    const float* al2 = (const float*)d_in[12];
    const float* ar2 = (const float*)d_in[13];
    const float* b2  = (const float*)d_in[14];
    float* out = (float*)d_out;

    float *p_feat, *p_hA, *p_hB;
    cudaGetSymbolAddress((void**)&p_feat, g_feat);
    cudaGetSymbolAddress((void**)&p_hA, g_hA);
    cudaGetSymbolAddress((void**)&p_hB, g_hB);

    // CSR build
    zero_kernel<<<(N_NODES + 255) / 256, 256>>>();
    hist_kernel<<<(N_EDGES + 255) / 256, 256>>>(dst);
    scan_chunksum_kernel<<<NCHUNK, 256>>>();
    scan_chunkoff_kernel<<<1, 64>>>();
    scan_final_kernel<<<NCHUNK, SCAN_CHUNK>>>();
    scatter_kernel<<<(N_EDGES + 255) / 256, 256>>>(src, dst);

    dim3 ggrid(256 / BN, (N_NODES + BM - 1) / BM);
    int nw4 = (N_NODES * HEADS + 7) / 8;
    int nw1 = (N_NODES + 7) / 8;

    // layer 0: 512 -> 4x64, relu
    gemm_tc_kernel<<<ggrid, 256>>>(feats, W0, p_feat, N_NODES, 512);
    elr4_kernel<<<nw4, 256>>>(al0, ar0);
    agg4_kernel<<<nw4, 256>>>(b0, p_hA);

    // layer 1: 256 -> 4x64, relu
    gemm_tc_kernel<<<ggrid, 256>>>(p_hA, W1, p_feat, N_NODES, 256);
    elr4_kernel<<<nw4, 256>>>(al1, ar1);
    agg4_kernel<<<nw4, 256>>>(b1, p_hB);

    // layer 2: 256 -> 1x256, no activation
    gemm_tc_kernel<<<ggrid, 256>>>(p_hB, W2, p_feat, N_NODES, 256);
    elr1_kernel<<<nw1, 256>>>(al2, ar2);
    agg1_kernel<<<nw1, 256>>>(b2, out);
}